// round 2
// baseline (speedup 1.0000x reference)
#include <cuda_runtime.h>
#include <math.h>

// Problem constants
#define M_TOTAL 32768      // 4 * 8192 rows
#define K_DIM_  1024       // d_model
#define N_TOTAL 4112       // 4*1024 + 16 output columns
#define SEC     1024       // section width for Q/K/V/G
#define Q_ELEMS 33554432ULL // 32768*1024 per big section

#define BM 128
#define BN 128
#define BK 16
#define TM 8
#define TN 8
#define PAD 4

__global__ __launch_bounds__(256, 2)
void gemm_fused_kernel(const float* __restrict__ X,
                       const float* __restrict__ W,
                       float* __restrict__ out)
{
    __shared__ float As[2][BK][BM + PAD];
    __shared__ float Bs[2][BK][BN + PAD];

    const int tid = threadIdx.x;
    const int tx = tid & 15;          // 0..15, column group
    const int ty = tid >> 4;          // 0..15, row group
    const int m0 = blockIdx.y * BM;
    const int n0 = blockIdx.x * BN;

    // Global->shared loader indices: 512 float4 per tile, 2 per thread
    const int lr  = tid >> 2;         // row within tile (0..63), +64 for second
    const int lc  = (tid & 3) * 4;    // col within BK (0,4,8,12)

    const int ar0 = m0 + lr;
    const int ar1 = m0 + lr + 64;
    const int br0 = n0 + lr;
    const int br1 = n0 + lr + 64;
    const bool b0ok = (br0 < N_TOTAL);
    const bool b1ok = (br1 < N_TOTAL);

    float acc[TM][TN];
    #pragma unroll
    for (int i = 0; i < TM; ++i)
        #pragma unroll
        for (int j = 0; j < TN; ++j) acc[i][j] = 0.0f;

    const float4 zero4 = make_float4(0.f, 0.f, 0.f, 0.f);

    // ---- prologue: load k-tile 0 ----
    float4 aR0 = *(const float4*)(X + (size_t)ar0 * K_DIM_ + lc);
    float4 aR1 = *(const float4*)(X + (size_t)ar1 * K_DIM_ + lc);
    float4 bR0 = b0ok ? *(const float4*)(W + (size_t)br0 * K_DIM_ + lc) : zero4;
    float4 bR1 = b1ok ? *(const float4*)(W + (size_t)br1 * K_DIM_ + lc) : zero4;

    As[0][lc + 0][lr] = aR0.x; As[0][lc + 1][lr] = aR0.y;
    As[0][lc + 2][lr] = aR0.z; As[0][lc + 3][lr] = aR0.w;
    As[0][lc + 0][lr + 64] = aR1.x; As[0][lc + 1][lr + 64] = aR1.y;
    As[0][lc + 2][lr + 64] = aR1.z; As[0][lc + 3][lr + 64] = aR1.w;
    Bs[0][lc + 0][lr] = bR0.x; Bs[0][lc + 1][lr] = bR0.y;
    Bs[0][lc + 2][lr] = bR0.z; Bs[0][lc + 3][lr] = bR0.w;
    Bs[0][lc + 0][lr + 64] = bR1.x; Bs[0][lc + 1][lr + 64] = bR1.y;
    Bs[0][lc + 2][lr + 64] = bR1.z; Bs[0][lc + 3][lr + 64] = bR1.w;
    __syncthreads();

    int cur = 0;
    const int NT = K_DIM_ / BK;   // 64
    #pragma unroll 1
    for (int kt = 0; kt < NT; ++kt) {
        // prefetch next k-tile into registers
        if (kt + 1 < NT) {
            const int kk = (kt + 1) * BK + lc;
            aR0 = *(const float4*)(X + (size_t)ar0 * K_DIM_ + kk);
            aR1 = *(const float4*)(X + (size_t)ar1 * K_DIM_ + kk);
            bR0 = b0ok ? *(const float4*)(W + (size_t)br0 * K_DIM_ + kk) : zero4;
            bR1 = b1ok ? *(const float4*)(W + (size_t)br1 * K_DIM_ + kk) : zero4;
        }

        // compute on current buffer
        #pragma unroll
        for (int k = 0; k < BK; ++k) {
            float a[TM], b[TN];
            *(float4*)&a[0] = *(const float4*)&As[cur][k][ty * TM];
            *(float4*)&a[4] = *(const float4*)&As[cur][k][ty * TM + 4];
            *(float4*)&b[0] = *(const float4*)&Bs[cur][k][tx * TN];
            *(float4*)&b[4] = *(const float4*)&Bs[cur][k][tx * TN + 4];
            #pragma unroll
            for (int i = 0; i < TM; ++i)
                #pragma unroll
                for (int j = 0; j < TN; ++j)
                    acc[i][j] = fmaf(a[i], b[j], acc[i][j]);
        }

        // store prefetched regs into the other buffer
        if (kt + 1 < NT) {
            const int nxt = cur ^ 1;
            As[nxt][lc + 0][lr] = aR0.x; As[nxt][lc + 1][lr] = aR0.y;
            As[nxt][lc + 2][lr] = aR0.z; As[nxt][lc + 3][lr] = aR0.w;
            As[nxt][lc + 0][lr + 64] = aR1.x; As[nxt][lc + 1][lr + 64] = aR1.y;
            As[nxt][lc + 2][lr + 64] = aR1.z; As[nxt][lc + 3][lr + 64] = aR1.w;
            Bs[nxt][lc + 0][lr] = bR0.x; Bs[nxt][lc + 1][lr] = bR0.y;
            Bs[nxt][lc + 2][lr] = bR0.z; Bs[nxt][lc + 3][lr] = bR0.w;
            Bs[nxt][lc + 0][lr + 64] = bR1.x; Bs[nxt][lc + 1][lr + 64] = bR1.y;
            Bs[nxt][lc + 2][lr + 64] = bR1.z; Bs[nxt][lc + 3][lr + 64] = bR1.w;
            __syncthreads();
            cur = nxt;
        }
    }

    // ---- fused epilogue: route to sections; K stays raw (pass 2 normalizes) ----
    #pragma unroll
    for (int i = 0; i < TM; ++i) {
        const size_t r = (size_t)(m0 + ty * TM + i);
        #pragma unroll
        for (int j = 0; j < TN; ++j) {
            const int o = n0 + tx * TN + j;
            if (o >= N_TOTAL) continue;
            const float v = acc[i][j];
            if (o < SEC) {
                out[r * SEC + o] = v;                                  // Q raw
            } else if (o < 2 * SEC) {
                out[Q_ELEMS + r * SEC + (o - SEC)] = v;                // K raw
            } else if (o < 3 * SEC) {
                out[2 * Q_ELEMS + r * SEC + (o - 2 * SEC)] = v;        // V
            } else if (o < 4 * SEC) {
                const float s = 1.0f / (1.0f + expf(-v));              // SiLU gate
                out[3 * Q_ELEMS + r * SEC + (o - 3 * SEC)] = v * s;
            } else {
                out[4 * Q_ELEMS + r * 16 + (o - 4 * SEC)] =            // sigmoid alpha
                    1.0f / (1.0f + expf(-v));
            }
        }
    }
}

// Pass 2: L2-normalize each FULL 1024-wide K row in place (reference uses
// jnp.linalg.norm over axis=-1 of the whole K section, NOT per head).
// One warp per row; each lane owns 32 contiguous floats (8 x float4).
__global__ __launch_bounds__(256)
void knorm_kernel(float* __restrict__ kptr)
{
    const int row  = blockIdx.x * (blockDim.x >> 5) + (threadIdx.x >> 5);
    const int lane = threadIdx.x & 31;
    float* p = kptr + (size_t)row * SEC + lane * 32;

    float4 v[8];
    float ss = 0.0f;
    #pragma unroll
    for (int i = 0; i < 8; ++i) {
        v[i] = *(const float4*)(p + i * 4);
        ss += v[i].x * v[i].x + v[i].y * v[i].y + v[i].z * v[i].z + v[i].w * v[i].w;
    }
    #pragma unroll
    for (int off = 16; off > 0; off >>= 1)
        ss += __shfl_xor_sync(0xFFFFFFFFu, ss, off);

    const float scale = 1.0f / fmaxf(sqrtf(ss), 1e-12f);
    #pragma unroll
    for (int i = 0; i < 8; ++i) {
        v[i].x *= scale; v[i].y *= scale; v[i].z *= scale; v[i].w *= scale;
        *(float4*)(p + i * 4) = v[i];
    }
}

extern "C" void kernel_launch(void* const* d_in, const int* in_sizes, int n_in,
                              void* d_out, int out_size)
{
    const float* x = (const float*)d_in[0];   // [4, 8192, 1024] fp32
    const float* W = (const float*)d_in[1];   // [4112, 1024] fp32
    float* out = (float*)d_out;

    dim3 grid((N_TOTAL + BN - 1) / BN, M_TOTAL / BM);  // 33 x 256
    gemm_fused_kernel<<<grid, 256>>>(x, W, out);

    // 32768 rows, one warp per row, 8 warps/block
    knorm_kernel<<<M_TOTAL / 8, 256>>>(out + Q_ELEMS);
}

// round 4
// speedup vs baseline: 2.8468x; 2.8468x over previous
#include <cuda_runtime.h>
#include <stdint.h>
#include <math.h>

// ---------------- problem constants ----------------
#define M_TOTAL 32768
#define KD      1024
#define N_TOTAL 4112
#define SEC_W   1024
#define Q_ELEMS 33554432ULL          // 32768*1024
#define NPAD    4352                 // 17 * 256

// ---------------- GEMM config ----------------
#define BM 128
#define BN 256
#define BK 16
#define STAGES 4
#define SA 20                         // smem row stride in floats (pad 4 -> conflict-free)
#define A_ST_FLOATS (BM * SA)         // 2560
#define B_ST_FLOATS (BN * SA)         // 5120
#define STAGE_FLOATS (A_ST_FLOATS + B_ST_FLOATS)   // 7680
#define SMEM_BYTES (STAGES * STAGE_FLOATS * 4)     // 122880

// ---------------- scratch: tf32-rounded fp32 copies ----------------
__device__ float g_Xr[(size_t)M_TOTAL * KD];   // 128 MB
__device__ float g_Wr[(size_t)NPAD * KD];      // 17.8 MB (rows >= 4112 zeroed)

// ---------------- helpers ----------------
__device__ __forceinline__ uint32_t smem_u32(const void* p) {
    uint32_t a;
    asm("{ .reg .u64 t; cvta.to.shared.u64 t, %1; cvt.u32.u64 %0, t; }" : "=r"(a) : "l"(p));
    return a;
}
__device__ __forceinline__ uint32_t f2tf32(float f) {
    uint32_t r;
    asm("cvt.rna.tf32.f32 %0, %1;" : "=r"(r) : "f"(f));
    return r;
}
__device__ __forceinline__ void cp16(uint32_t dst, const float* src) {
    asm volatile("cp.async.cg.shared.global [%0], [%1], 16;" :: "r"(dst), "l"(src) : "memory");
}
#define CP_COMMIT() asm volatile("cp.async.commit_group;" ::: "memory")
#define CP_WAIT2()  asm volatile("cp.async.wait_group 2;" ::: "memory")

__device__ __forceinline__ void mma_tf32(float* d, const uint32_t* a, const uint32_t* b) {
    asm volatile(
        "mma.sync.aligned.m16n8k8.row.col.f32.tf32.tf32.f32 "
        "{%0,%1,%2,%3}, {%4,%5,%6,%7}, {%8,%9}, {%0,%1,%2,%3};"
        : "+f"(d[0]), "+f"(d[1]), "+f"(d[2]), "+f"(d[3])
        : "r"(a[0]), "r"(a[1]), "r"(a[2]), "r"(a[3]), "r"(b[0]), "r"(b[1]));
}

// ---------------- tf32 rounding pre-passes ----------------
__global__ __launch_bounds__(256)
void cvt_x_kernel(const float* __restrict__ X)
{
    const size_t i = ((size_t)blockIdx.x * 256 + threadIdx.x) * 4;
    float4 v = *(const float4*)(X + i);
    v.x = __uint_as_float(f2tf32(v.x));
    v.y = __uint_as_float(f2tf32(v.y));
    v.z = __uint_as_float(f2tf32(v.z));
    v.w = __uint_as_float(f2tf32(v.w));
    *(float4*)(g_Xr + i) = v;
}

__global__ __launch_bounds__(256)
void cvt_w_kernel(const float* __restrict__ W)
{
    const size_t i = ((size_t)blockIdx.x * 256 + threadIdx.x) * 4;
    const int row = (int)(i >> 10);
    float4 v = make_float4(0.f, 0.f, 0.f, 0.f);
    if (row < N_TOTAL) {
        v = *(const float4*)(W + i);
        v.x = __uint_as_float(f2tf32(v.x));
        v.y = __uint_as_float(f2tf32(v.y));
        v.z = __uint_as_float(f2tf32(v.z));
        v.w = __uint_as_float(f2tf32(v.w));
    }
    *(float4*)(g_Wr + i) = v;
}

// ---------------- fused epilogue store ----------------
__device__ __forceinline__ void store_pair(float* __restrict__ out, size_t r, int gc,
                                           float v0, float v1)
{
    if (gc < 4096) {
        const int sec = gc >> 10;
        float* dst = out + (size_t)sec * Q_ELEMS + r * SEC_W + (gc & 1023);
        if (sec == 3) {                                   // SiLU gate
            v0 = v0 / (1.0f + expf(-v0));
            v1 = v1 / (1.0f + expf(-v1));
        }
        *(float2*)dst = make_float2(v0, v1);
    } else if (gc < N_TOTAL) {                            // sigmoid alpha
        float* dst = out + 4 * Q_ELEMS + r * 16 + (gc - 4096);
        *(float2*)dst = make_float2(1.0f / (1.0f + expf(-v0)),
                                    1.0f / (1.0f + expf(-v1)));
    }
}

// ---------------- main GEMM (tf32 mma.sync, 4-stage cp.async) ----------------
__global__ __launch_bounds__(256)
void gemm_tc_kernel(float* __restrict__ out)
{
    extern __shared__ float sm[];
    const uint32_t smbase = smem_u32(sm);

    const int tid = threadIdx.x;
    const int lane = tid & 31;
    const int wid = tid >> 5;
    const int wm = wid >> 2;           // 0..1  (64 rows each)
    const int wn = wid & 3;            // 0..3  (64 cols each)
    const int g  = lane >> 2;          // groupID
    const int t4 = lane & 3;           // thread-in-group
    const int m0 = blockIdx.y * BM;
    const int n0 = blockIdx.x * BN;

    float acc[4][8][4];
    #pragma unroll
    for (int mi = 0; mi < 4; ++mi)
        #pragma unroll
        for (int ni = 0; ni < 8; ++ni)
            #pragma unroll
            for (int j = 0; j < 4; ++j) acc[mi][ni][j] = 0.0f;

    // stage loader: 1536 16B chunks (A: 512, B: 1024), 6 per thread
    auto load_stage = [&](int st, int kt) {
        const uint32_t base = smbase + (uint32_t)(st * STAGE_FLOATS * 4);
        #pragma unroll
        for (int i = 0; i < 6; ++i) {
            const int c = tid + i * 256;
            if (c < 512) {
                const int row = c >> 2, q = c & 3;
                cp16(base + (uint32_t)((row * SA + q * 4) * 4),
                     g_Xr + (size_t)(m0 + row) * KD + kt * BK + q * 4);
            } else {
                const int c2 = c - 512;
                const int row = c2 >> 2, q = c2 & 3;
                cp16(base + (uint32_t)((A_ST_FLOATS + row * SA + q * 4) * 4),
                     g_Wr + (size_t)(n0 + row) * KD + kt * BK + q * 4);
            }
        }
    };

    // prologue: prefetch 3 stages
    load_stage(0, 0); CP_COMMIT();
    load_stage(1, 1); CP_COMMIT();
    load_stage(2, 2); CP_COMMIT();
    CP_WAIT2();
    __syncthreads();

    const int NT = KD / BK;   // 64
    #pragma unroll 1
    for (int kt = 0; kt < NT; ++kt) {
        const int st = kt & 3;
        const float* As = sm + st * STAGE_FLOATS;
        const float* Bs = As + A_ST_FLOATS;

        #pragma unroll
        for (int ks = 0; ks < 2; ++ks) {
            uint32_t a[4][4], b[8][2];
            #pragma unroll
            for (int mi = 0; mi < 4; ++mi) {
                const int base = (wm * 64 + mi * 16 + g) * SA + ks * 8 + t4;
                a[mi][0] = __float_as_uint(As[base]);
                a[mi][1] = __float_as_uint(As[base + 8 * SA]);
                a[mi][2] = __float_as_uint(As[base + 4]);
                a[mi][3] = __float_as_uint(As[base + 8 * SA + 4]);
            }
            #pragma unroll
            for (int ni = 0; ni < 8; ++ni) {
                const int base = (wn * 64 + ni * 8 + g) * SA + ks * 8 + t4;
                b[ni][0] = __float_as_uint(Bs[base]);
                b[ni][1] = __float_as_uint(Bs[base + 4]);
            }
            #pragma unroll
            for (int mi = 0; mi < 4; ++mi)
                #pragma unroll
                for (int ni = 0; ni < 8; ++ni)
                    mma_tf32(acc[mi][ni], a[mi], b[ni]);
        }

        if (kt + 3 < NT) load_stage((kt + 3) & 3, kt + 3);
        CP_COMMIT();
        CP_WAIT2();
        __syncthreads();
    }

    // ---- fused epilogue: direct fragment stores with routing/activations ----
    #pragma unroll
    for (int mi = 0; mi < 4; ++mi) {
        const size_t r0 = (size_t)(m0 + wm * 64 + mi * 16 + g);
        #pragma unroll
        for (int ni = 0; ni < 8; ++ni) {
            const int gc = n0 + wn * 64 + ni * 8 + 2 * t4;
            store_pair(out, r0,     gc, acc[mi][ni][0], acc[mi][ni][1]);
            store_pair(out, r0 + 8, gc, acc[mi][ni][2], acc[mi][ni][3]);
        }
    }
}

// ---------------- pass 2: L2-normalize full 1024-wide K rows ----------------
__global__ __launch_bounds__(256)
void knorm_kernel(float* __restrict__ kptr)
{
    const int row  = blockIdx.x * (blockDim.x >> 5) + (threadIdx.x >> 5);
    const int lane = threadIdx.x & 31;
    float* p = kptr + (size_t)row * SEC_W + lane * 32;

    float4 v[8];
    float ss = 0.0f;
    #pragma unroll
    for (int i = 0; i < 8; ++i) {
        v[i] = *(const float4*)(p + i * 4);
        ss += v[i].x * v[i].x + v[i].y * v[i].y + v[i].z * v[i].z + v[i].w * v[i].w;
    }
    #pragma unroll
    for (int off = 16; off > 0; off >>= 1)
        ss += __shfl_xor_sync(0xFFFFFFFFu, ss, off);

    const float scale = 1.0f / fmaxf(sqrtf(ss), 1e-12f);
    #pragma unroll
    for (int i = 0; i < 8; ++i) {
        v[i].x *= scale; v[i].y *= scale; v[i].z *= scale; v[i].w *= scale;
        *(float4*)(p + i * 4) = v[i];
    }
}

extern "C" void kernel_launch(void* const* d_in, const int* in_sizes, int n_in,
                              void* d_out, int out_size)
{
    const float* x = (const float*)d_in[0];   // [4, 8192, 1024] fp32
    const float* W = (const float*)d_in[1];   // [4112, 1024] fp32
    float* out = (float*)d_out;

    cudaFuncSetAttribute(gemm_tc_kernel,
                         cudaFuncAttributeMaxDynamicSharedMemorySize, SMEM_BYTES);

    // 1) round inputs to tf32 (zero-pad W rows to 4352)
    cvt_x_kernel<<<(M_TOTAL * KD / 4) / 256, 256>>>(x);
    cvt_w_kernel<<<(NPAD * KD / 4) / 256, 256>>>(W);

    // 2) tf32 mma.sync GEMM + fused routing/activation epilogue
    dim3 grid(NPAD / BN, M_TOTAL / BM);     // 17 x 256
    gemm_tc_kernel<<<grid, 256, SMEM_BYTES>>>(out);

    // 3) K row L2-normalization
    knorm_kernel<<<M_TOTAL / 8, 256>>>(out + Q_ELEMS);
}

// round 5
// speedup vs baseline: 3.7119x; 1.3039x over previous
#include <cuda_runtime.h>
#include <stdint.h>
#include <math.h>

// ---------------- problem constants ----------------
#define M_TOTAL 32768
#define KD      1024
#define N_TOTAL 4112
#define SEC_W   1024
#define Q_ELEMS 33554432ULL          // 32768*1024
#define NPAD    4352                 // 17 * 256

// ---------------- GEMM config ----------------
#define BM 128
#define BN 256
#define BK 16
#define STAGES 4
#define NTHREADS 512                  // 16 warps: 2 (M) x 8 (N), warp tile 64x32
#define SA 20                         // smem row stride in floats (pad -> conflict-free)
#define A_ST_FLOATS (BM * SA)         // 2560
#define B_ST_FLOATS (BN * SA)         // 5120
#define STAGE_FLOATS (A_ST_FLOATS + B_ST_FLOATS)   // 7680
#define SMEM_BYTES (STAGES * STAGE_FLOATS * 4)     // 122880

// ---------------- scratch: tf32-rounded fp32 copies ----------------
__device__ float g_Xr[(size_t)M_TOTAL * KD];   // 128 MB
__device__ float g_Wr[(size_t)NPAD * KD];      // 17.8 MB (rows >= 4112 zeroed)

// ---------------- helpers ----------------
__device__ __forceinline__ uint32_t smem_u32(const void* p) {
    uint32_t a;
    asm("{ .reg .u64 t; cvta.to.shared.u64 t, %1; cvt.u32.u64 %0, t; }" : "=r"(a) : "l"(p));
    return a;
}
__device__ __forceinline__ uint32_t f2tf32(float f) {
    uint32_t r;
    asm("cvt.rna.tf32.f32 %0, %1;" : "=r"(r) : "f"(f));
    return r;
}
__device__ __forceinline__ void cp16(uint32_t dst, const float* src) {
    asm volatile("cp.async.cg.shared.global [%0], [%1], 16;" :: "r"(dst), "l"(src) : "memory");
}
#define CP_COMMIT() asm volatile("cp.async.commit_group;" ::: "memory")
#define CP_WAIT2()  asm volatile("cp.async.wait_group 2;" ::: "memory")

__device__ __forceinline__ void ldsm_x4(uint32_t* r, uint32_t addr) {
    asm volatile("ldmatrix.sync.aligned.m8n8.x4.shared.b16 {%0,%1,%2,%3}, [%4];"
        : "=r"(r[0]), "=r"(r[1]), "=r"(r[2]), "=r"(r[3]) : "r"(addr));
}
__device__ __forceinline__ void ldsm_x2(uint32_t* r, uint32_t addr) {
    asm volatile("ldmatrix.sync.aligned.m8n8.x2.shared.b16 {%0,%1}, [%2];"
        : "=r"(r[0]), "=r"(r[1]) : "r"(addr));
}
__device__ __forceinline__ void mma_tf32(float* d, const uint32_t* a, const uint32_t* b) {
    asm volatile(
        "mma.sync.aligned.m16n8k8.row.col.f32.tf32.tf32.f32 "
        "{%0,%1,%2,%3}, {%4,%5,%6,%7}, {%8,%9}, {%0,%1,%2,%3};"
        : "+f"(d[0]), "+f"(d[1]), "+f"(d[2]), "+f"(d[3])
        : "r"(a[0]), "r"(a[1]), "r"(a[2]), "r"(a[3]), "r"(b[0]), "r"(b[1]));
}

// ---------------- tf32 rounding pre-passes ----------------
__global__ __launch_bounds__(256)
void cvt_x_kernel(const float* __restrict__ X)
{
    const size_t i = ((size_t)blockIdx.x * 256 + threadIdx.x) * 4;
    float4 v = *(const float4*)(X + i);
    v.x = __uint_as_float(f2tf32(v.x));
    v.y = __uint_as_float(f2tf32(v.y));
    v.z = __uint_as_float(f2tf32(v.z));
    v.w = __uint_as_float(f2tf32(v.w));
    *(float4*)(g_Xr + i) = v;
}

__global__ __launch_bounds__(256)
void cvt_w_kernel(const float* __restrict__ W)
{
    const size_t i = ((size_t)blockIdx.x * 256 + threadIdx.x) * 4;
    const int row = (int)(i >> 10);
    float4 v = make_float4(0.f, 0.f, 0.f, 0.f);
    if (row < N_TOTAL) {
        v = *(const float4*)(W + i);
        v.x = __uint_as_float(f2tf32(v.x));
        v.y = __uint_as_float(f2tf32(v.y));
        v.z = __uint_as_float(f2tf32(v.z));
        v.w = __uint_as_float(f2tf32(v.w));
    }
    *(float4*)(g_Wr + i) = v;
}

// ---------------- fused epilogue store ----------------
__device__ __forceinline__ void store_pair(float* __restrict__ out, size_t r, int gc,
                                           float v0, float v1)
{
    if (gc < 4096) {
        const int sec = gc >> 10;
        float* dst = out + (size_t)sec * Q_ELEMS + r * SEC_W + (gc & 1023);
        if (sec == 3) {                                   // SiLU gate
            v0 = v0 / (1.0f + expf(-v0));
            v1 = v1 / (1.0f + expf(-v1));
        }
        *(float2*)dst = make_float2(v0, v1);
    } else if (gc < N_TOTAL) {                            // sigmoid alpha
        float* dst = out + 4 * Q_ELEMS + r * 16 + (gc - 4096);
        *(float2*)dst = make_float2(1.0f / (1.0f + expf(-v0)),
                                    1.0f / (1.0f + expf(-v1)));
    }
}

// ---------------- main GEMM (tf32 mma.sync + ldmatrix, 4-stage cp.async) ----------------
__global__ __launch_bounds__(NTHREADS, 1)
void gemm_tc_kernel(float* __restrict__ out)
{
    extern __shared__ float sm[];
    const uint32_t smbase = smem_u32(sm);

    const int tid = threadIdx.x;
    const int lane = tid & 31;
    const int wid = tid >> 5;
    const int wm = wid >> 3;           // 0..1  (64 rows each)
    const int wn = wid & 7;            // 0..7  (32 cols each)
    const int g  = lane >> 2;          // groupID
    const int t4 = lane & 3;           // thread-in-group
    const int m0 = blockIdx.y * BM;
    const int n0 = blockIdx.x * BN;

    // ldmatrix per-thread source offsets (in floats, within stage)
    const int a_lrow = wm * 64 + (lane & 7) + ((lane >> 3) & 1) * 8;   // + mi*16
    const int a_lcol = ((lane >> 4) & 1) * 4;                          // + ks*8
    const int t16 = lane & 15;
    const int b_lrow = wn * 32 + (t16 & 7);                            // + ni*8
    const int b_lcol = ((t16 >> 3) & 1) * 4;                           // + ks*8

    float acc[4][4][4];
    #pragma unroll
    for (int mi = 0; mi < 4; ++mi)
        #pragma unroll
        for (int ni = 0; ni < 4; ++ni)
            #pragma unroll
            for (int j = 0; j < 4; ++j) acc[mi][ni][j] = 0.0f;

    // stage loader: 1536 16B chunks (A: 512, B: 1024), 3 per thread
    auto load_stage = [&](int st, int kt) {
        const uint32_t base = smbase + (uint32_t)(st * STAGE_FLOATS * 4);
        #pragma unroll
        for (int i = 0; i < 3; ++i) {
            const int c = tid + i * NTHREADS;
            if (c < 512) {
                const int row = c >> 2, q = c & 3;
                cp16(base + (uint32_t)((row * SA + q * 4) * 4),
                     g_Xr + (size_t)(m0 + row) * KD + kt * BK + q * 4);
            } else {
                const int c2 = c - 512;
                const int row = c2 >> 2, q = c2 & 3;
                cp16(base + (uint32_t)((A_ST_FLOATS + row * SA + q * 4) * 4),
                     g_Wr + (size_t)(n0 + row) * KD + kt * BK + q * 4);
            }
        }
    };

    // prologue: prefetch 3 stages
    load_stage(0, 0); CP_COMMIT();
    load_stage(1, 1); CP_COMMIT();
    load_stage(2, 2); CP_COMMIT();
    CP_WAIT2();
    __syncthreads();

    const int NT = KD / BK;   // 64
    #pragma unroll 1
    for (int kt = 0; kt < NT; ++kt) {
        const int st = kt & 3;
        const uint32_t aStage = smbase + (uint32_t)(st * STAGE_FLOATS * 4);
        const uint32_t bStage = aStage + (uint32_t)(A_ST_FLOATS * 4);

        #pragma unroll
        for (int ks = 0; ks < 2; ++ks) {
            uint32_t a[4][4], b[4][2];
            #pragma unroll
            for (int mi = 0; mi < 4; ++mi)
                ldsm_x4(a[mi], aStage +
                    (uint32_t)(((a_lrow + mi * 16) * SA + ks * 8 + a_lcol) * 4));
            #pragma unroll
            for (int ni = 0; ni < 4; ++ni)
                ldsm_x2(b[ni], bStage +
                    (uint32_t)(((b_lrow + ni * 8) * SA + ks * 8 + b_lcol) * 4));
            #pragma unroll
            for (int mi = 0; mi < 4; ++mi)
                #pragma unroll
                for (int ni = 0; ni < 4; ++ni)
                    mma_tf32(acc[mi][ni], a[mi], b[ni]);
        }

        if (kt + 3 < NT) load_stage((kt + 3) & 3, kt + 3);
        CP_COMMIT();
        CP_WAIT2();
        __syncthreads();
    }

    // ---- fused epilogue: direct fragment stores with routing/activations ----
    #pragma unroll
    for (int mi = 0; mi < 4; ++mi) {
        const size_t r0 = (size_t)(m0 + wm * 64 + mi * 16 + g);
        #pragma unroll
        for (int ni = 0; ni < 4; ++ni) {
            const int gc = n0 + wn * 32 + ni * 8 + 2 * t4;
            store_pair(out, r0,     gc, acc[mi][ni][0], acc[mi][ni][1]);
            store_pair(out, r0 + 8, gc, acc[mi][ni][2], acc[mi][ni][3]);
        }
    }
}

// ---------------- pass 2: L2-normalize full 1024-wide K rows ----------------
__global__ __launch_bounds__(256)
void knorm_kernel(float* __restrict__ kptr)
{
    const int row  = blockIdx.x * (blockDim.x >> 5) + (threadIdx.x >> 5);
    const int lane = threadIdx.x & 31;
    float* p = kptr + (size_t)row * SEC_W + lane * 32;

    float4 v[8];
    float ss = 0.0f;
    #pragma unroll
    for (int i = 0; i < 8; ++i) {
        v[i] = *(const float4*)(p + i * 4);
        ss += v[i].x * v[i].x + v[i].y * v[i].y + v[i].z * v[i].z + v[i].w * v[i].w;
    }
    #pragma unroll
    for (int off = 16; off > 0; off >>= 1)
        ss += __shfl_xor_sync(0xFFFFFFFFu, ss, off);

    const float scale = 1.0f / fmaxf(sqrtf(ss), 1e-12f);
    #pragma unroll
    for (int i = 0; i < 8; ++i) {
        v[i].x *= scale; v[i].y *= scale; v[i].z *= scale; v[i].w *= scale;
        *(float4*)(p + i * 4) = v[i];
    }
}

extern "C" void kernel_launch(void* const* d_in, const int* in_sizes, int n_in,
                              void* d_out, int out_size)
{
    const float* x = (const float*)d_in[0];   // [4, 8192, 1024] fp32
    const float* W = (const float*)d_in[1];   // [4112, 1024] fp32
    float* out = (float*)d_out;

    cudaFuncSetAttribute(gemm_tc_kernel,
                         cudaFuncAttributeMaxDynamicSharedMemorySize, SMEM_BYTES);

    // 1) round inputs to tf32 (zero-pad W rows to 4352)
    cvt_x_kernel<<<(M_TOTAL * KD / 4) / 256, 256>>>(x);
    cvt_w_kernel<<<(NPAD * KD / 4) / 256, 256>>>(W);

    // 2) tf32 mma.sync GEMM + fused routing/activation epilogue
    dim3 grid(NPAD / BN, M_TOTAL / BM);     // 17 x 256
    gemm_tc_kernel<<<grid, NTHREADS, SMEM_BYTES>>>(out);

    // 3) K row L2-normalization
    knorm_kernel<<<M_TOTAL / 8, 256>>>(out + Q_ELEMS);
}